// round 1
// baseline (speedup 1.0000x reference)
#include <cuda_runtime.h>
#include <math.h>

#define NSAMP 8192
#define HIDN  256
#define CHS   ((size_t)NSAMP * HIDN)   // per-channel element stride

// Jet channel order: 0=value, 1=d/dx0, 2=d/dx1, 3=d/dt, 4=d2/dx0dx0, 5=d2/dx0dx1, 6=d2/dx1dx1
__device__ float  g_bufA[7 * NSAMP * HIDN];
__device__ float  g_bufB[7 * NSAMP * HIDN];
__device__ double g_acc[5];   // S_res0^2, S_res1^2, S_respf^2, S_energy, S_irr

// ---------------------------------------------------------------------------
// zero the accumulators (graph-replay safe)
__global__ void k_zero() {
    if (threadIdx.x < 5) g_acc[threadIdx.x] = 0.0;
}

// ---------------------------------------------------------------------------
// Layer 0: input jets -> linear(W0,b0) -> tanh jet. Input jets are trivial:
// value=(x0,x1,t), tangents are unit vectors, second order = 0.
__global__ void k_layer0(const float* __restrict__ W0, const float* __restrict__ b0,
                         const float* __restrict__ x,  const float* __restrict__ t) {
    size_t g = (size_t)blockIdx.x * blockDim.x + threadIdx.x; // n*256 + j
    int j = (int)(g & (HIDN - 1));
    int n = (int)(g >> 8);
    float x0 = x[2 * n], x1 = x[2 * n + 1], tv = t[n];
    float w0 = W0[j], w1 = W0[HIDN + j], w2 = W0[2 * HIDN + j];
    float zv = fmaf(x0, w0, fmaf(x1, w1, fmaf(tv, w2, b0[j])));
    float y   = tanhf(zv);
    float yp  = 1.0f - y * y;
    float ypp = -2.0f * y * yp;
    g_bufA[g]           = y;
    g_bufA[g + CHS]     = yp * w0;
    g_bufA[g + 2 * CHS] = yp * w1;
    g_bufA[g + 3 * CHS] = yp * w2;
    g_bufA[g + 4 * CHS] = ypp * w0 * w0;
    g_bufA[g + 5 * CHS] = ypp * w0 * w1;
    g_bufA[g + 6 * CHS] = ypp * w1 * w1;
}

// ---------------------------------------------------------------------------
// SGEMM: C[M x 256] = A[M x 256] * B[256 x 256], M = 7*8192 = 57344.
// 128x128 block tile, BK=8, 256 threads, 8x8 register tile.
__global__ void __launch_bounds__(256) k_sgemm(const float* __restrict__ A,
                                               const float* __restrict__ B,
                                               float* __restrict__ C) {
    const int K = 256, NN = 256;
    __shared__ float As[8][128];
    __shared__ float Bs[8][128];
    int tid  = threadIdx.x;
    int row0 = blockIdx.y * 128;
    int col0 = blockIdx.x * 128;

    int arow = tid >> 1;            // 0..127
    int acol = (tid & 1) << 2;      // 0 or 4
    int brow = tid >> 5;            // 0..7
    int bcol = (tid & 31) << 2;     // 0..124

    int tr = (tid >> 4) << 3;       // row of 8x8 tile
    int tc = (tid & 15) << 3;       // col of 8x8 tile

    float acc[8][8];
#pragma unroll
    for (int i = 0; i < 8; i++)
#pragma unroll
        for (int jj = 0; jj < 8; jj++) acc[i][jj] = 0.0f;

    const float* Aptr = A + (size_t)(row0 + arow) * K + acol;
    const float* Bptr = B + (size_t)brow * NN + col0 + bcol;

    for (int k0 = 0; k0 < K; k0 += 8) {
        float4 av = *(const float4*)(Aptr + k0);
        float4 bv = *(const float4*)(Bptr + (size_t)k0 * NN);
        As[acol + 0][arow] = av.x;
        As[acol + 1][arow] = av.y;
        As[acol + 2][arow] = av.z;
        As[acol + 3][arow] = av.w;
        *(float4*)&Bs[brow][bcol] = bv;
        __syncthreads();
#pragma unroll
        for (int kk = 0; kk < 8; kk++) {
            float a[8], b[8];
#pragma unroll
            for (int i = 0; i < 8; i++) a[i] = As[kk][tr + i];
#pragma unroll
            for (int jj = 0; jj < 8; jj++) b[jj] = Bs[kk][tc + jj];
#pragma unroll
            for (int i = 0; i < 8; i++)
#pragma unroll
                for (int jj = 0; jj < 8; jj++) acc[i][jj] = fmaf(a[i], b[jj], acc[i][jj]);
        }
        __syncthreads();
    }
#pragma unroll
    for (int i = 0; i < 8; i++) {
        float* Crow = C + (size_t)(row0 + tr + i) * NN + col0 + tc;
#pragma unroll
        for (int jj = 0; jj < 8; jj += 4) {
            float4 v = make_float4(acc[i][jj], acc[i][jj + 1], acc[i][jj + 2], acc[i][jj + 3]);
            *(float4*)(Crow + jj) = v;
        }
    }
}

// ---------------------------------------------------------------------------
// tanh jet activation (in place), bias added to the value channel only.
__global__ void k_act(float* __restrict__ Z, const float* __restrict__ bias) {
    size_t g = (size_t)blockIdx.x * blockDim.x + threadIdx.x;
    int j = (int)(g & (HIDN - 1));
    float zv  = Z[g] + bias[j];
    float zg1 = Z[g + CHS], zg2 = Z[g + 2 * CHS], zg3 = Z[g + 3 * CHS];
    float zs11 = Z[g + 4 * CHS], zs12 = Z[g + 5 * CHS], zs22 = Z[g + 6 * CHS];
    float y   = tanhf(zv);
    float yp  = 1.0f - y * y;
    float ypp = -2.0f * y * yp;
    Z[g]           = y;
    Z[g + CHS]     = yp * zg1;
    Z[g + 2 * CHS] = yp * zg2;
    Z[g + 3 * CHS] = yp * zg3;
    Z[g + 4 * CHS] = fmaf(ypp * zg1, zg1, yp * zs11);
    Z[g + 5 * CHS] = fmaf(ypp * zg1, zg2, yp * zs12);
    Z[g + 6 * CHS] = fmaf(ypp * zg2, zg2, yp * zs22);
}

// ---------------------------------------------------------------------------
// Epilogue: final linear layer (256 -> 3) on all 7 jet channels, then the full
// physics (stress divergence, phase-field residual, energy, irreversibility),
// then block-reduce into the 5 global accumulators. One warp per sample.
__global__ void __launch_bounds__(256) k_epi(const float* __restrict__ H,
                                             const float* __restrict__ W4,
                                             const float* __restrict__ b4,
                                             const float* __restrict__ x,
                                             const float* __restrict__ t) {
    __shared__ float  w4s[768];
    __shared__ float  b4s[3];
    __shared__ double sacc[5];
    int tid = threadIdx.x;
    if (tid < 5) sacc[tid] = 0.0;
    for (int i = tid; i < 768; i += 256) w4s[i] = W4[i];
    if (tid < 3) b4s[tid] = b4[tid];
    __syncthreads();

    int warp = tid >> 5, lane = tid & 31;
    int n = blockIdx.x * 8 + warp;

    float o[7][3];
#pragma unroll
    for (int c = 0; c < 7; c++)
#pragma unroll
        for (int a = 0; a < 3; a++) o[c][a] = 0.0f;

    const float* hb = H + (size_t)n * HIDN;
    for (int k = lane; k < HIDN; k += 32) {
        float wa = w4s[k * 3 + 0], wb = w4s[k * 3 + 1], wc = w4s[k * 3 + 2];
#pragma unroll
        for (int c = 0; c < 7; c++) {
            float hv = hb[(size_t)c * CHS + k];
            o[c][0] = fmaf(hv, wa, o[c][0]);
            o[c][1] = fmaf(hv, wb, o[c][1]);
            o[c][2] = fmaf(hv, wc, o[c][2]);
        }
    }
#pragma unroll
    for (int c = 0; c < 7; c++)
#pragma unroll
        for (int a = 0; a < 3; a++)
#pragma unroll
            for (int off = 16; off > 0; off >>= 1)
                o[c][a] += __shfl_xor_sync(0xFFFFFFFFu, o[c][a], off);

    if (lane == 0) {
        // sol values and derivatives
        float s0  = o[0][0] + b4s[0];
        float s1v = o[0][1] + b4s[1];
        float s2v = o[0][2] + b4s[2];
        float D00 = o[1][0], D01 = o[2][0], D0t = o[3][0];
        float S000 = o[4][0], S001 = o[5][0], S011 = o[6][0];
        float D10 = o[1][1], D11 = o[2][1];
        float S100 = o[4][1], S101 = o[5][1], S111 = o[6][1];
        float D20 = o[1][2], D21 = o[2][2];
        float S200 = o[4][2], S201 = o[5][2], S211 = o[6][2];

        float x1 = x[2 * n + 1];
        float tt = t[n];
        float q  = x1 * (x1 - 1.0f);
        float qp = 2.0f * x1 - 1.0f;
        float t3 = tt / 3.0f;

        // displacement derivatives (x only, t fixed)
        float ux0 = t3 * q * D10;
        float ux1 = t3 * (qp * s1v + q * D11);
        float uy0 = tt * q * D20;
        float uy1 = tt * (qp * s2v + q * D21) + tt;

        float e00 = ux0, e11 = uy1, e01 = 0.5f * (ux1 + uy0);

        float ux00 = t3 * q * S100;
        float ux01 = t3 * (qp * D10 + q * S101);
        float ux11 = t3 * (2.0f * s1v + 2.0f * qp * D11 + q * S111);
        float uy00 = tt * q * S200;
        float uy01 = tt * (qp * D20 + q * S201);
        float uy11 = tt * (2.0f * s2v + 2.0f * qp * D21 + q * S211);

        float e00_0 = ux00, e00_1 = ux01;
        float e11_0 = uy01, e11_1 = uy11;
        float e01_0 = 0.5f * (ux01 + uy00);
        float e01_1 = 0.5f * (ux11 + uy01);

        float trc  = e00 + e11;
        float tr_0 = e00_0 + e11_0;
        float tr_1 = e00_1 + e11_1;

        // phi and derivatives
        float phi = 1.0f / (1.0f + expf(-s0));
        float sp  = phi * (1.0f - phi);
        float spp = sp * (1.0f - 2.0f * phi);
        float p0 = sp * D00, p1 = sp * D01, pt = sp * D0t;
        float p00 = spp * D00 * D00 + sp * S000;
        float p11 = spp * D01 * D01 + sp * S011;
        float lap = p00 + p11;

        // psi_pos / psi_neg (LAMBDA=MU=1, DIM=2 -> k=2)
        float A  = fmaxf(trc, 0.0f);
        float Bn = fmaxf(-trc, 0.0f);
        float ppos = (trc > 0.0f) ? 1.0f : 0.0f;
        float pneg = (trc < 0.0f) ? 1.0f : 0.0f;
        float dd = e00 - e11;

        float omp = 1.0f - phi;
        float h   = omp * omp;
        float g   = h + 1e-6f;
        float hp0 = -2.0f * omp * p0;
        float hp1 = -2.0f * omp * p1;

        float P00 = 2.0f * A + dd;
        float P11 = 2.0f * A - dd;
        float P01 = 2.0f * e01;
        float s00 = g * P00 - 2.0f * Bn;
        float s11c = g * P11 - 2.0f * Bn;
        float s01 = g * P01;

        float P00_0 = 2.0f * ppos * tr_0 + (e00_0 - e11_0);
        float P11_1 = 2.0f * ppos * tr_1 - (e00_1 - e11_1);
        float P01_0 = 2.0f * e01_0;
        float P01_1 = 2.0f * e01_1;

        float s00_0 = hp0 * P00 + g * P00_0 + 2.0f * pneg * tr_0;
        float s11_1 = hp1 * P11 + g * P11_1 + 2.0f * pneg * tr_1;
        float s01_0 = hp0 * P01 + g * P01_0;
        float s01_1 = hp1 * P01 + g * P01_1;

        float res0 = hp0 * s00 + h * s00_0 + hp1 * s01 + h * s01_1;
        float res1 = hp0 * s01 + h * s01_0 + hp1 * s11c + h * s11_1;

        float psip = A * A + 0.5f * dd * dd + 2.0f * e01 * e01;
        float psin = Bn * Bn;

        const float GCc = 0.0027f, Lc = 0.02f;
        float pf = GCc * (phi / Lc - Lc * lap) - 2.0f * omp * psip;
        float dphidt = pt;
        bool mask_pos = (fabsf(dphidt) <= 1e-3f) && (fabsf(phi - 1.0f) > 1e-3f);
        bool mask_neg = (fabsf(phi - 1.0f) <= 1e-3f);
        float respf = mask_pos ? fmaxf(-pf, 0.0f) : (mask_neg ? fmaxf(pf, 0.0f) : pf);

        float rese = omp * 2.0f * psip + psin
                   + GCc * (phi * phi / (2.0f * Lc) + 0.5f * Lc * (p0 * p0 + p1 * p1));
        float rirr = fmaxf(-dphidt, 0.0f);

        atomicAdd(&sacc[0], (double)(res0 * res0));
        atomicAdd(&sacc[1], (double)(res1 * res1));
        atomicAdd(&sacc[2], (double)(respf * respf));
        atomicAdd(&sacc[3], (double)rese);
        atomicAdd(&sacc[4], (double)rirr);
    }
    __syncthreads();
    if (tid < 5) atomicAdd(&g_acc[tid], sacc[tid]);
}

// ---------------------------------------------------------------------------
__global__ void k_final(float* __restrict__ out) {
    double S0 = g_acc[0], S1 = g_acc[1], Spf = g_acc[2], Se = g_acc[3], Si = g_acc[4];
    double Nn = (double)NSAMP;
    double mse0 = S0 / Nn, mse1 = S1 / Nn;
    double m  = 0.5 * (mse0 + mse1);
    double w0 = m / (mse0 + 1e-6);
    double w1 = m / (mse1 + 1e-6);
    out[0] = (float)(w0 * mse0 + w1 * mse1);
    out[1] = (float)(Spf / Nn);
    out[2] = (float)log(Se);
    out[3] = (float)(Si / Nn);
}

// ---------------------------------------------------------------------------
extern "C" void kernel_launch(void* const* d_in, const int* in_sizes, int n_in,
                              void* d_out, int out_size) {
    const float *W[5], *b[5];
    // Two possible metadata orderings: interleaved (W0,b0,W1,b1,...) per
    // setup_inputs dict order, or flat (W0..W4,b0..b4) per signature order.
    // Disambiguate via in_sizes[1]: 256 -> interleaved (b0), 65536 -> flat (W1).
    if (n_in >= 2 && in_sizes[1] == HIDN) {
        for (int i = 0; i < 5; i++) {
            W[i] = (const float*)d_in[2 * i];
            b[i] = (const float*)d_in[2 * i + 1];
        }
    } else {
        for (int i = 0; i < 5; i++) {
            W[i] = (const float*)d_in[i];
            b[i] = (const float*)d_in[5 + i];
        }
    }
    const float* x = (const float*)d_in[10];
    const float* t = (const float*)d_in[11];

    float* pA; float* pB;
    cudaGetSymbolAddress((void**)&pA, g_bufA);
    cudaGetSymbolAddress((void**)&pB, g_bufB);

    k_zero<<<1, 32>>>();
    k_layer0<<<NSAMP, 256>>>(W[0], b[0], x, t);

    dim3 gg(2, (7 * NSAMP) / 128);   // 256/128 col tiles, 57344/128 row tiles
    k_sgemm<<<gg, 256>>>(pA, W[1], pB);
    k_act<<<NSAMP, 256>>>(pB, b[1]);
    k_sgemm<<<gg, 256>>>(pB, W[2], pA);
    k_act<<<NSAMP, 256>>>(pA, b[2]);
    k_sgemm<<<gg, 256>>>(pA, W[3], pB);
    k_act<<<NSAMP, 256>>>(pB, b[3]);

    k_epi<<<NSAMP / 8, 256>>>(pB, W[4], b[4], x, t);
    k_final<<<1, 1>>>((float*)d_out);
}

// round 3
// speedup vs baseline: 2.1628x; 2.1628x over previous
#include <cuda_runtime.h>
#include <cuda_bf16.h>
#include <cstdint>
#include <math.h>

#define NSAMP 8192
#define HIDN  256
#define MTOT  (7 * NSAMP)       // 57344 rows, interleaved: row = n*7 + c
#define MT    112               // rows per CTA = 16 samples * 7 channels
#define SPC   16                // samples per CTA

// Jet channels: 0=val, 1=d/dx0, 2=d/dx1, 3=d/dt, 4=dx0dx0, 5=dx0dx1, 6=dx1dx1
__device__ __align__(256) __nv_bfloat16 g_Ahi[MTOT * HIDN];
__device__ __align__(256) __nv_bfloat16 g_Alo[MTOT * HIDN];
__device__ __align__(256) __nv_bfloat16 g_Wthi[3][HIDN * HIDN];  // W^T: [n][k]
__device__ __align__(256) __nv_bfloat16 g_Wtlo[3][HIDN * HIDN];
__device__ double g_acc[5];

// ---------------------------------------------------------------------------
__device__ __forceinline__ uint32_t smem_u32(const void* p) {
    uint32_t a;
    asm("{ .reg .u64 t; cvta.to.shared.u64 t, %1; cvt.u32.u64 %0, t; }" : "=r"(a) : "l"(p));
    return a;
}
__device__ __forceinline__ uint32_t sw128(uint32_t o) { return o ^ ((o >> 3) & 0x70); }

__device__ __forceinline__ void cpasync16(uint32_t s, const void* g) {
    asm volatile("cp.async.cg.shared.global [%0], [%1], 16;" :: "r"(s), "l"(g));
}
#define CP_COMMIT() asm volatile("cp.async.commit_group;" ::: "memory")

__device__ __forceinline__ void ldsm_x4(uint32_t* r, uint32_t a) {
    asm volatile("ldmatrix.sync.aligned.m8n8.x4.shared.b16 {%0,%1,%2,%3}, [%4];"
                 : "=r"(r[0]), "=r"(r[1]), "=r"(r[2]), "=r"(r[3]) : "r"(a));
}
__device__ __forceinline__ void ldsm_x2(uint32_t* r, uint32_t a) {
    asm volatile("ldmatrix.sync.aligned.m8n8.x2.shared.b16 {%0,%1}, [%2];"
                 : "=r"(r[0]), "=r"(r[1]) : "r"(a));
}
__device__ __forceinline__ void mma16816(float* d, const uint32_t* a, const uint32_t* b) {
    asm volatile(
        "mma.sync.aligned.m16n8k16.row.col.f32.bf16.bf16.f32 "
        "{%0,%1,%2,%3}, {%4,%5,%6,%7}, {%8,%9}, {%0,%1,%2,%3};"
        : "+f"(d[0]), "+f"(d[1]), "+f"(d[2]), "+f"(d[3])
        : "r"(a[0]), "r"(a[1]), "r"(a[2]), "r"(a[3]), "r"(b[0]), "r"(b[1]));
}

// ---------------------------------------------------------------------------
__global__ void k_zero() { if (threadIdx.x < 5) g_acc[threadIdx.x] = 0.0; }

// transpose + bf16-split the 3 hidden weight matrices
__global__ void k_prepW(const float* __restrict__ W1, const float* __restrict__ W2,
                        const float* __restrict__ W3) {
    int w = blockIdx.z;
    const float* W = (w == 0) ? W1 : ((w == 1) ? W2 : W3);
    int n = blockIdx.x, k = threadIdx.x;
    float v = W[k * HIDN + n];
    __nv_bfloat16 h = __float2bfloat16(v);
    g_Wthi[w][n * HIDN + k] = h;
    g_Wtlo[w][n * HIDN + k] = __float2bfloat16(v - __bfloat162float(h));
}

__device__ __forceinline__ void store_split(size_t idx, float v) {
    __nv_bfloat16 h = __float2bfloat16(v);
    g_Ahi[idx] = h;
    g_Alo[idx] = __float2bfloat16(v - __bfloat162float(h));
}

// Layer 0: input jets -> linear(W0,b0) -> tanh jet, interleaved row layout
__global__ void k_layer0(const float* __restrict__ W0, const float* __restrict__ b0,
                         const float* __restrict__ x,  const float* __restrict__ t) {
    int n = blockIdx.x, j = threadIdx.x;
    float x0 = x[2 * n], x1 = x[2 * n + 1], tv = t[n];
    float w0 = W0[j], w1 = W0[HIDN + j], w2 = W0[2 * HIDN + j];
    float zv = fmaf(x0, w0, fmaf(x1, w1, fmaf(tv, w2, b0[j])));
    float y = tanhf(zv);
    float yp = 1.0f - y * y;
    float ypp = -2.0f * y * yp;
    size_t base = ((size_t)n * 7) * HIDN + j;
    store_split(base,            y);
    store_split(base + HIDN,     yp * w0);
    store_split(base + 2 * HIDN, yp * w1);
    store_split(base + 3 * HIDN, yp * w2);
    store_split(base + 4 * HIDN, ypp * w0 * w0);
    store_split(base + 5 * HIDN, ypp * w0 * w1);
    store_split(base + 6 * HIDN, ypp * w1 * w1);
}

// ---------------------------------------------------------------------------
// Fused GEMM+activation layer:
//   Z[112 x 256] = (Ahi+Alo)[112 x 256] @ (Whi+Wlo)^T   (3-product bf16 split)
//   then jet-tanh activation across the 7 channels of each of the 16 samples,
//   bf16 hi/lo written back in place over g_Ahi/g_Alo.
#define AB   14336                  // one A half-tile: 112 rows x 128B
#define BB   32768                  // one B half-tile: 256 rows x 128B
#define BUF  (2 * AB + 2 * BB)      // 94208
#define SMEMT (2 * BUF)             // 188416
#define ZSTRIDE 260

__global__ void __launch_bounds__(256) k_gemm(const __nv_bfloat16* __restrict__ Bhi,
                                              const __nv_bfloat16* __restrict__ Blo,
                                              const float* __restrict__ bias) {
    extern __shared__ char smem[];
    uint32_t sb = smem_u32(smem);
    int tid = threadIdx.x;
    int warp = tid >> 5, lane = tid & 31;
    int row0 = blockIdx.x * MT;

    float acc[7][4][4];
#pragma unroll
    for (int mt = 0; mt < 7; mt++)
#pragma unroll
        for (int nt = 0; nt < 4; nt++)
#pragma unroll
            for (int e = 0; e < 4; e++) acc[mt][nt][e] = 0.0f;

    // ---- chunk loader (k-chunk of 64, hi & lo halves of A and B) ----
    auto load_chunk = [&](int c) {
        uint32_t base = sb + (c & 1) * BUF;
        int k0 = c * 64;
        // A: 112 rows x 2 halves x 8 16B units
        for (int idx = tid; idx < 1792; idx += 256) {
            int r = idx >> 4, h = (idx >> 3) & 1, u = idx & 7;
            const __nv_bfloat16* gp = (h ? g_Alo : g_Ahi)
                                    + (size_t)(row0 + r) * HIDN + k0 + u * 8;
            cpasync16(base + h * AB + sw128(r * 128 + u * 16), gp);
        }
        // B: 256 rows x 2 halves x 8 16B units
        for (int idx = tid; idx < 4096; idx += 256) {
            int r = idx >> 4, h = (idx >> 3) & 1, u = idx & 7;
            const __nv_bfloat16* gp = (h ? Blo : Bhi) + (size_t)r * HIDN + k0 + u * 8;
            cpasync16(base + 2 * AB + h * BB + sw128(r * 128 + u * 16), gp);
        }
        CP_COMMIT();
    };

    load_chunk(0);

    int l8 = lane & 7;
    int qa_m8  = ((lane >> 3) & 1) * 8;    // A ldmatrix: +8 row for mats 1,3
    int qa_k16 = (lane >> 4) * 16;         // A ldmatrix: +16B for mats 2,3
    int qb_k16 = ((lane >> 3) & 1) * 16;   // B ldmatrix: +16B for mat 1

    for (int c = 0; c < 4; c++) {
        if (c < 3) load_chunk(c + 1);
        if (c < 3) asm volatile("cp.async.wait_group 1;" ::: "memory");
        else       asm volatile("cp.async.wait_group 0;" ::: "memory");
        __syncthreads();

        uint32_t bufb = sb + (c & 1) * BUF;
#pragma unroll
        for (int p = 0; p < 3; p++) {
            uint32_t ab = bufb + ((p == 2) ? AB : 0);
            uint32_t bb = bufb + 2 * AB + ((p == 1) ? BB : 0);
#pragma unroll
            for (int ks = 0; ks < 4; ks++) {
                uint32_t af[7][4];
#pragma unroll
                for (int mt = 0; mt < 7; mt++) {
                    int r = mt * 16 + qa_m8 + l8;
                    ldsm_x4(af[mt], ab + sw128(r * 128 + ks * 32 + qa_k16));
                }
                uint32_t bf[4][2];
#pragma unroll
                for (int nt = 0; nt < 4; nt++) {
                    int r = warp * 32 + nt * 8 + l8;
                    ldsm_x2(bf[nt], bb + sw128(r * 128 + ks * 32 + qb_k16));
                }
#pragma unroll
                for (int mt = 0; mt < 7; mt++)
#pragma unroll
                    for (int nt = 0; nt < 4; nt++)
                        mma16816(acc[mt][nt], af[mt], bf[nt]);
            }
        }
        __syncthreads();
    }

    // ---- epilogue: accums -> smem z, jet activation, bf16 split out ----
    float* zb = (float*)smem;
#pragma unroll
    for (int mt = 0; mt < 7; mt++)
#pragma unroll
        for (int nt = 0; nt < 4; nt++)
#pragma unroll
            for (int e = 0; e < 4; e++) {
                int r = mt * 16 + (lane >> 2) + ((e >> 1) << 3);
                int col = warp * 32 + nt * 8 + ((lane & 3) << 1) + (e & 1);
                zb[r * ZSTRIDE + col] = acc[mt][nt][e];
            }
    __syncthreads();

    for (int i = tid; i < SPC * HIDN; i += 256) {
        int nl = i >> 8, j = i & 255;
        const float* zrow = zb + (nl * 7) * ZSTRIDE + j;
        float zv  = zrow[0] + bias[j];
        float zg1 = zrow[ZSTRIDE],     zg2 = zrow[2 * ZSTRIDE], zg3 = zrow[3 * ZSTRIDE];
        float zs11 = zrow[4 * ZSTRIDE], zs12 = zrow[5 * ZSTRIDE], zs22 = zrow[6 * ZSTRIDE];
        float y = tanhf(zv);
        float yp = 1.0f - y * y;
        float ypp = -2.0f * y * yp;
        size_t gbase = ((size_t)(row0 + nl * 7)) * HIDN + j;
        store_split(gbase,            y);
        store_split(gbase + HIDN,     yp * zg1);
        store_split(gbase + 2 * HIDN, yp * zg2);
        store_split(gbase + 3 * HIDN, yp * zg3);
        store_split(gbase + 4 * HIDN, fmaf(ypp * zg1, zg1, yp * zs11));
        store_split(gbase + 5 * HIDN, fmaf(ypp * zg1, zg2, yp * zs12));
        store_split(gbase + 6 * HIDN, fmaf(ypp * zg2, zg2, yp * zs22));
    }
}

// ---------------------------------------------------------------------------
// Physics epilogue: final 256->3 layer on all 7 jet channels + residuals.
__global__ void __launch_bounds__(256) k_epi(const float* __restrict__ W4,
                                             const float* __restrict__ b4,
                                             const float* __restrict__ x,
                                             const float* __restrict__ t) {
    __shared__ float  w4s[768];
    __shared__ float  b4s[3];
    __shared__ double sacc[5];
    int tid = threadIdx.x;
    if (tid < 5) sacc[tid] = 0.0;
    for (int i = tid; i < 768; i += 256) w4s[i] = W4[i];
    if (tid < 3) b4s[tid] = b4[tid];
    __syncthreads();

    int warp = tid >> 5, lane = tid & 31;
    int n = blockIdx.x * 8 + warp;

    float o[7][3];
#pragma unroll
    for (int c = 0; c < 7; c++)
#pragma unroll
        for (int a = 0; a < 3; a++) o[c][a] = 0.0f;

    for (int k = lane; k < HIDN; k += 32) {
        float wa = w4s[k * 3 + 0], wb = w4s[k * 3 + 1], wc = w4s[k * 3 + 2];
        size_t bidx = ((size_t)n * 7) * HIDN + k;
#pragma unroll
        for (int c = 0; c < 7; c++) {
            size_t ii = bidx + (size_t)c * HIDN;
            float hv = __bfloat162float(g_Ahi[ii]) + __bfloat162float(g_Alo[ii]);
            o[c][0] = fmaf(hv, wa, o[c][0]);
            o[c][1] = fmaf(hv, wb, o[c][1]);
            o[c][2] = fmaf(hv, wc, o[c][2]);
        }
    }
#pragma unroll
    for (int c = 0; c < 7; c++)
#pragma unroll
        for (int a = 0; a < 3; a++)
#pragma unroll
            for (int off = 16; off > 0; off >>= 1)
                o[c][a] += __shfl_xor_sync(0xFFFFFFFFu, o[c][a], off);

    if (lane == 0) {
        float s0  = o[0][0] + b4s[0];
        float s1v = o[0][1] + b4s[1];
        float s2v = o[0][2] + b4s[2];
        float D00 = o[1][0], D01 = o[2][0], D0t = o[3][0];
        float S000 = o[4][0], S011 = o[6][0];
        float D10 = o[1][1], D11 = o[2][1];
        float S100 = o[4][1], S101 = o[5][1], S111 = o[6][1];
        float D20 = o[1][2], D21 = o[2][2];
        float S200 = o[4][2], S201 = o[5][2], S211 = o[6][2];

        float x1 = x[2 * n + 1];
        float tt = t[n];
        float q  = x1 * (x1 - 1.0f);
        float qp = 2.0f * x1 - 1.0f;
        float t3 = tt / 3.0f;

        float ux0 = t3 * q * D10;
        float ux1 = t3 * (qp * s1v + q * D11);
        float uy0 = tt * q * D20;
        float uy1 = tt * (qp * s2v + q * D21) + tt;

        float e00 = ux0, e11 = uy1, e01 = 0.5f * (ux1 + uy0);

        float ux00 = t3 * q * S100;
        float ux01 = t3 * (qp * D10 + q * S101);
        float ux11 = t3 * (2.0f * s1v + 2.0f * qp * D11 + q * S111);
        float uy00 = tt * q * S200;
        float uy01 = tt * (qp * D20 + q * S201);
        float uy11 = tt * (2.0f * s2v + 2.0f * qp * D21 + q * S211);

        float e00_0 = ux00, e00_1 = ux01;
        float e11_0 = uy01, e11_1 = uy11;
        float e01_0 = 0.5f * (ux01 + uy00);
        float e01_1 = 0.5f * (ux11 + uy01);

        float trc  = e00 + e11;
        float tr_0 = e00_0 + e11_0;
        float tr_1 = e00_1 + e11_1;

        float phi = 1.0f / (1.0f + expf(-s0));
        float sp  = phi * (1.0f - phi);
        float spp = sp * (1.0f - 2.0f * phi);
        float p0 = sp * D00, p1 = sp * D01, pt = sp * D0t;
        float p00 = spp * D00 * D00 + sp * S000;
        float p11 = spp * D01 * D01 + sp * S011;
        float lap = p00 + p11;

        float A  = fmaxf(trc, 0.0f);
        float Bn = fmaxf(-trc, 0.0f);
        float ppos = (trc > 0.0f) ? 1.0f : 0.0f;
        float pneg = (trc < 0.0f) ? 1.0f : 0.0f;
        float dd = e00 - e11;

        float omp = 1.0f - phi;
        float h   = omp * omp;
        float g   = h + 1e-6f;
        float hp0 = -2.0f * omp * p0;
        float hp1 = -2.0f * omp * p1;

        float P00 = 2.0f * A + dd;
        float P11 = 2.0f * A - dd;
        float P01 = 2.0f * e01;
        float s00 = g * P00 - 2.0f * Bn;
        float s11c = g * P11 - 2.0f * Bn;
        float s01 = g * P01;

        float P00_0 = 2.0f * ppos * tr_0 + (e00_0 - e11_0);
        float P11_1 = 2.0f * ppos * tr_1 - (e00_1 - e11_1);
        float P01_0 = 2.0f * e01_0;
        float P01_1 = 2.0f * e01_1;

        float s00_0 = hp0 * P00 + g * P00_0 + 2.0f * pneg * tr_0;
        float s11_1 = hp1 * P11 + g * P11_1 + 2.0f * pneg * tr_1;
        float s01_0 = hp0 * P01 + g * P01_0;
        float s01_1 = hp1 * P01 + g * P01_1;

        float res0 = hp0 * s00 + h * s00_0 + hp1 * s01 + h * s01_1;
        float res1 = hp0 * s01 + h * s01_0 + hp1 * s11c + h * s11_1;

        float psip = A * A + 0.5f * dd * dd + 2.0f * e01 * e01;
        float psin = Bn * Bn;

        const float GCc = 0.0027f, Lc = 0.02f;
        float pf = GCc * (phi / Lc - Lc * lap) - 2.0f * omp * psip;
        float dphidt = pt;
        bool mask_pos = (fabsf(dphidt) <= 1e-3f) && (fabsf(phi - 1.0f) > 1e-3f);
        bool mask_neg = (fabsf(phi - 1.0f) <= 1e-3f);
        float respf = mask_pos ? fmaxf(-pf, 0.0f) : (mask_neg ? fmaxf(pf, 0.0f) : pf);

        float rese = omp * 2.0f * psip + psin
                   + GCc * (phi * phi / (2.0f * Lc) + 0.5f * Lc * (p0 * p0 + p1 * p1));
        float rirr = fmaxf(-dphidt, 0.0f);

        atomicAdd(&sacc[0], (double)(res0 * res0));
        atomicAdd(&sacc[1], (double)(res1 * res1));
        atomicAdd(&sacc[2], (double)(respf * respf));
        atomicAdd(&sacc[3], (double)rese);
        atomicAdd(&sacc[4], (double)rirr);
    }
    __syncthreads();
    if (tid < 5) atomicAdd(&g_acc[tid], sacc[tid]);
}

// ---------------------------------------------------------------------------
__global__ void k_final(float* __restrict__ out) {
    double S0 = g_acc[0], S1 = g_acc[1], Spf = g_acc[2], Se = g_acc[3], Si = g_acc[4];
    double Nn = (double)NSAMP;
    double mse0 = S0 / Nn, mse1 = S1 / Nn;
    double m  = 0.5 * (mse0 + mse1);
    double w0 = m / (mse0 + 1e-6);
    double w1 = m / (mse1 + 1e-6);
    out[0] = (float)(w0 * mse0 + w1 * mse1);
    out[1] = (float)(Spf / Nn);
    out[2] = (float)log(Se);
    out[3] = (float)(Si / Nn);
}

// ---------------------------------------------------------------------------
extern "C" void kernel_launch(void* const* d_in, const int* in_sizes, int n_in,
                              void* d_out, int out_size) {
    const float *W[5], *b[5];
    if (n_in >= 2 && in_sizes[1] == HIDN) {
        for (int i = 0; i < 5; i++) {
            W[i] = (const float*)d_in[2 * i];
            b[i] = (const float*)d_in[2 * i + 1];
        }
    } else {
        for (int i = 0; i < 5; i++) {
            W[i] = (const float*)d_in[i];
            b[i] = (const float*)d_in[5 + i];
        }
    }
    const float* x = (const float*)d_in[10];
    const float* t = (const float*)d_in[11];

    __nv_bfloat16 *pWhi, *pWlo;
    cudaGetSymbolAddress((void**)&pWhi, g_Wthi);
    cudaGetSymbolAddress((void**)&pWlo, g_Wtlo);

    static bool attr_done = false;
    if (!attr_done) {
        cudaFuncSetAttribute(k_gemm, cudaFuncAttributeMaxDynamicSharedMemorySize, SMEMT);
        attr_done = true;
    }

    k_zero<<<1, 32>>>();
    k_prepW<<<dim3(HIDN, 1, 3), HIDN>>>(W[1], W[2], W[3]);
    k_layer0<<<NSAMP, 256>>>(W[0], b[0], x, t);

    const int GRID = MTOT / MT;   // 512
    k_gemm<<<GRID, 256, SMEMT>>>(pWhi,                 pWlo,                 b[1]);
    k_gemm<<<GRID, 256, SMEMT>>>(pWhi + HIDN * HIDN,   pWlo + HIDN * HIDN,   b[2]);
    k_gemm<<<GRID, 256, SMEMT>>>(pWhi + 2 * HIDN * HIDN, pWlo + 2 * HIDN * HIDN, b[3]);

    k_epi<<<NSAMP / 8, 256>>>(W[4], b[4], x, t);
    k_final<<<1, 1>>>((float*)d_out);
}

// round 4
// speedup vs baseline: 2.7959x; 1.2928x over previous
#include <cuda_runtime.h>
#include <cuda_bf16.h>
#include <cstdint>
#include <math.h>

#define NSAMP 8192
#define HIDN  256
#define MTOT  (7 * NSAMP)       // 57344 rows, interleaved: row = n*7 + c
#define MT    112               // rows per CTA = 16 samples * 7 channels
#define SPC   16                // samples per CTA

// Jet channels: 0=val, 1=d/dx0, 2=d/dx1, 3=d/dt, 4=dx0dx0, 5=dx0dx1, 6=dx1dx1
__device__ __align__(256) __nv_bfloat16 g_Ahi[MTOT * HIDN];
__device__ __align__(256) __nv_bfloat16 g_Alo[MTOT * HIDN];
__device__ __align__(256) __nv_bfloat16 g_Wt[3][HIDN * HIDN];  // W^T bf16: [n][k]
__device__ double g_acc[5];

// ---------------------------------------------------------------------------
__device__ __forceinline__ uint32_t smem_u32(const void* p) {
    uint32_t a;
    asm("{ .reg .u64 t; cvta.to.shared.u64 t, %1; cvt.u32.u64 %0, t; }" : "=r"(a) : "l"(p));
    return a;
}
__device__ __forceinline__ uint32_t sw128(uint32_t o) { return o ^ ((o >> 3) & 0x70); }

__device__ __forceinline__ void cpasync16(uint32_t s, const void* g) {
    asm volatile("cp.async.cg.shared.global [%0], [%1], 16;" :: "r"(s), "l"(g));
}
#define CP_COMMIT() asm volatile("cp.async.commit_group;" ::: "memory")

__device__ __forceinline__ void ldsm_x4(uint32_t* r, uint32_t a) {
    asm volatile("ldmatrix.sync.aligned.m8n8.x4.shared.b16 {%0,%1,%2,%3}, [%4];"
                 : "=r"(r[0]), "=r"(r[1]), "=r"(r[2]), "=r"(r[3]) : "r"(a));
}
__device__ __forceinline__ void ldsm_x2(uint32_t* r, uint32_t a) {
    asm volatile("ldmatrix.sync.aligned.m8n8.x2.shared.b16 {%0,%1}, [%2];"
                 : "=r"(r[0]), "=r"(r[1]) : "r"(a));
}
__device__ __forceinline__ void mma16816(float* d, const uint32_t* a, const uint32_t* b) {
    asm volatile(
        "mma.sync.aligned.m16n8k16.row.col.f32.bf16.bf16.f32 "
        "{%0,%1,%2,%3}, {%4,%5,%6,%7}, {%8,%9}, {%0,%1,%2,%3};"
        : "+f"(d[0]), "+f"(d[1]), "+f"(d[2]), "+f"(d[3])
        : "r"(a[0]), "r"(a[1]), "r"(a[2]), "r"(a[3]), "r"(b[0]), "r"(b[1]));
}

// ---------------------------------------------------------------------------
// transpose + bf16-round the 3 hidden weight matrices; also zero accumulators
__global__ void k_prepW(const float* __restrict__ W1, const float* __restrict__ W2,
                        const float* __restrict__ W3) {
    int w = blockIdx.z;
    const float* W = (w == 0) ? W1 : ((w == 1) ? W2 : W3);
    int n = blockIdx.x, k = threadIdx.x;
    g_Wt[w][n * HIDN + k] = __float2bfloat16(W[k * HIDN + n]);
    if (w == 0 && n == 0 && k < 5) g_acc[k] = 0.0;
}

__device__ __forceinline__ void store_split(size_t idx, float v) {
    __nv_bfloat16 h = __float2bfloat16(v);
    g_Ahi[idx] = h;
    g_Alo[idx] = __float2bfloat16(v - __bfloat162float(h));
}

// Layer 0: input jets -> linear(W0,b0) -> tanh jet, interleaved row layout
__global__ void k_layer0(const float* __restrict__ W0, const float* __restrict__ b0,
                         const float* __restrict__ x,  const float* __restrict__ t) {
    int n = blockIdx.x, j = threadIdx.x;
    float x0 = x[2 * n], x1 = x[2 * n + 1], tv = t[n];
    float w0 = W0[j], w1 = W0[HIDN + j], w2 = W0[2 * HIDN + j];
    float zv = fmaf(x0, w0, fmaf(x1, w1, fmaf(tv, w2, b0[j])));
    float y = tanhf(zv);
    float yp = 1.0f - y * y;
    float ypp = -2.0f * y * yp;
    size_t base = ((size_t)n * 7) * HIDN + j;
    store_split(base,            y);
    store_split(base + HIDN,     yp * w0);
    store_split(base + 2 * HIDN, yp * w1);
    store_split(base + 3 * HIDN, yp * w2);
    store_split(base + 4 * HIDN, ypp * w0 * w0);
    store_split(base + 5 * HIDN, ypp * w0 * w1);
    store_split(base + 6 * HIDN, ypp * w1 * w1);
}

// ---------------------------------------------------------------------------
// Fused GEMM+activation layer, B resident in smem:
//   Z[112 x 256] = (Ahi+Alo)[112 x 256] @ Wt^T      (2-product split-A)
// smem: A double-buffer [2][2][112x128B] = 57344, then B [4 kc][256x128B] = 131072
#define ACH   14336                      // one A half-chunk: 112 rows x 128B
#define ABUF  (2 * ACH)                  // hi+lo for one k-chunk
#define SB_B  (2 * ABUF)                 // 57344 : B base
#define SMEMT (SB_B + 4 * 32768)         // 188416
#define ZSTRIDE 260

__global__ void __launch_bounds__(256) k_gemm(const __nv_bfloat16* __restrict__ Bw,
                                              const float* __restrict__ bias) {
    extern __shared__ char smem[];
    uint32_t sb = smem_u32(smem);
    int tid = threadIdx.x;
    int warp = tid >> 5, lane = tid & 31;
    int row0 = blockIdx.x * MT;

    float acc[7][4][4];
#pragma unroll
    for (int mt = 0; mt < 7; mt++)
#pragma unroll
        for (int nt = 0; nt < 4; nt++)
#pragma unroll
            for (int e = 0; e < 4; e++) acc[mt][nt][e] = 0.0f;

    // ---- B: whole 256x256 bf16 weight tile, resident ----
    for (int idx = tid; idx < 8192; idx += 256) {
        int kc = idx >> 11, r = (idx >> 3) & 255, u = idx & 7;
        cpasync16(sb + SB_B + kc * 32768 + sw128(r * 128 + u * 16),
                  Bw + (size_t)r * HIDN + kc * 64 + u * 8);
    }
    CP_COMMIT();

    auto load_A = [&](int c) {
        uint32_t base = sb + (c & 1) * ABUF;
        int k0 = c * 64;
        for (int idx = tid; idx < 1792; idx += 256) {
            int r = idx >> 4, h = (idx >> 3) & 1, u = idx & 7;
            const __nv_bfloat16* gp = (h ? g_Alo : g_Ahi)
                                    + (size_t)(row0 + r) * HIDN + k0 + u * 8;
            cpasync16(base + h * ACH + sw128(r * 128 + u * 16), gp);
        }
        CP_COMMIT();
    };

    load_A(0);

    int l8 = lane & 7;
    int qa_m8  = ((lane >> 3) & 1) * 8;    // A ldmatrix: +8 row for mats 1,3
    int qa_k16 = (lane >> 4) * 16;         // A ldmatrix: +16B for mats 2,3
    int qb_k16 = ((lane >> 3) & 1) * 16;   // B ldmatrix: +16B for mat 1

    for (int c = 0; c < 4; c++) {
        if (c < 3) { load_A(c + 1); asm volatile("cp.async.wait_group 1;" ::: "memory"); }
        else       {                asm volatile("cp.async.wait_group 0;" ::: "memory"); }
        __syncthreads();

        uint32_t ahb = sb + (c & 1) * ABUF;
        uint32_t alb = ahb + ACH;
        uint32_t bb  = sb + SB_B + c * 32768;
#pragma unroll
        for (int ks = 0; ks < 4; ks++) {
            uint32_t bf[4][2];
#pragma unroll
            for (int nt = 0; nt < 4; nt++) {
                int r = warp * 32 + nt * 8 + l8;
                ldsm_x2(bf[nt], bb + sw128(r * 128 + ks * 32 + qb_k16));
            }
            uint32_t afh[7][4];
#pragma unroll
            for (int mt = 0; mt < 7; mt++) {
                int r = mt * 16 + qa_m8 + l8;
                ldsm_x4(afh[mt], ahb + sw128(r * 128 + ks * 32 + qa_k16));
            }
            uint32_t afl[7][4];
#pragma unroll
            for (int mt = 0; mt < 7; mt++) {
                int r = mt * 16 + qa_m8 + l8;
                ldsm_x4(afl[mt], alb + sw128(r * 128 + ks * 32 + qa_k16));
            }
#pragma unroll
            for (int mt = 0; mt < 7; mt++)
#pragma unroll
                for (int nt = 0; nt < 4; nt++)
                    mma16816(acc[mt][nt], afh[mt], bf[nt]);
#pragma unroll
            for (int mt = 0; mt < 7; mt++)
#pragma unroll
                for (int nt = 0; nt < 4; nt++)
                    mma16816(acc[mt][nt], afl[mt], bf[nt]);
        }
        __syncthreads();
    }

    // ---- epilogue: accums -> z staging (reuses B region), jet activation ----
    float* zb = (float*)(smem + SB_B);
#pragma unroll
    for (int mt = 0; mt < 7; mt++)
#pragma unroll
        for (int nt = 0; nt < 4; nt++)
#pragma unroll
            for (int e = 0; e < 4; e++) {
                int r = mt * 16 + (lane >> 2) + ((e >> 1) << 3);
                int col = warp * 32 + nt * 8 + ((lane & 3) << 1) + (e & 1);
                zb[r * ZSTRIDE + col] = acc[mt][nt][e];
            }
    __syncthreads();

    for (int i = tid; i < SPC * HIDN; i += 256) {
        int nl = i >> 8, j = i & 255;
        const float* zrow = zb + (nl * 7) * ZSTRIDE + j;
        float zv  = zrow[0] + bias[j];
        float zg1 = zrow[ZSTRIDE],      zg2 = zrow[2 * ZSTRIDE], zg3 = zrow[3 * ZSTRIDE];
        float zs11 = zrow[4 * ZSTRIDE], zs12 = zrow[5 * ZSTRIDE], zs22 = zrow[6 * ZSTRIDE];
        float y = tanhf(zv);
        float yp = 1.0f - y * y;
        float ypp = -2.0f * y * yp;
        size_t gbase = ((size_t)(row0 + nl * 7)) * HIDN + j;
        store_split(gbase,            y);
        store_split(gbase + HIDN,     yp * zg1);
        store_split(gbase + 2 * HIDN, yp * zg2);
        store_split(gbase + 3 * HIDN, yp * zg3);
        store_split(gbase + 4 * HIDN, fmaf(ypp * zg1, zg1, yp * zs11));
        store_split(gbase + 5 * HIDN, fmaf(ypp * zg1, zg2, yp * zs12));
        store_split(gbase + 6 * HIDN, fmaf(ypp * zg2, zg2, yp * zs22));
    }
}

// ---------------------------------------------------------------------------
// Physics epilogue: final 256->3 layer on all 7 jet channels + residuals.
__global__ void __launch_bounds__(256) k_epi(const float* __restrict__ W4,
                                             const float* __restrict__ b4,
                                             const float* __restrict__ x,
                                             const float* __restrict__ t) {
    __shared__ float  w4s[768];
    __shared__ float  b4s[3];
    __shared__ double sacc[5];
    int tid = threadIdx.x;
    if (tid < 5) sacc[tid] = 0.0;
    for (int i = tid; i < 768; i += 256) w4s[i] = W4[i];
    if (tid < 3) b4s[tid] = b4[tid];
    __syncthreads();

    int warp = tid >> 5, lane = tid & 31;
    int n = blockIdx.x * 8 + warp;

    float o[7][3];
#pragma unroll
    for (int c = 0; c < 7; c++)
#pragma unroll
        for (int a = 0; a < 3; a++) o[c][a] = 0.0f;

    for (int k = lane; k < HIDN; k += 32) {
        float wa = w4s[k * 3 + 0], wb = w4s[k * 3 + 1], wc = w4s[k * 3 + 2];
        size_t bidx = ((size_t)n * 7) * HIDN + k;
#pragma unroll
        for (int c = 0; c < 7; c++) {
            size_t ii = bidx + (size_t)c * HIDN;
            float hv = __bfloat162float(g_Ahi[ii]) + __bfloat162float(g_Alo[ii]);
            o[c][0] = fmaf(hv, wa, o[c][0]);
            o[c][1] = fmaf(hv, wb, o[c][1]);
            o[c][2] = fmaf(hv, wc, o[c][2]);
        }
    }
#pragma unroll
    for (int c = 0; c < 7; c++)
#pragma unroll
        for (int a = 0; a < 3; a++)
#pragma unroll
            for (int off = 16; off > 0; off >>= 1)
                o[c][a] += __shfl_xor_sync(0xFFFFFFFFu, o[c][a], off);

    if (lane == 0) {
        float s0  = o[0][0] + b4s[0];
        float s1v = o[0][1] + b4s[1];
        float s2v = o[0][2] + b4s[2];
        float D00 = o[1][0], D01 = o[2][0], D0t = o[3][0];
        float S000 = o[4][0], S011 = o[6][0];
        float D10 = o[1][1], D11 = o[2][1];
        float S100 = o[4][1], S101 = o[5][1], S111 = o[6][1];
        float D20 = o[1][2], D21 = o[2][2];
        float S200 = o[4][2], S201 = o[5][2], S211 = o[6][2];

        float x1 = x[2 * n + 1];
        float tt = t[n];
        float q  = x1 * (x1 - 1.0f);
        float qp = 2.0f * x1 - 1.0f;
        float t3 = tt / 3.0f;

        float ux0 = t3 * q * D10;
        float ux1 = t3 * (qp * s1v + q * D11);
        float uy0 = tt * q * D20;
        float uy1 = tt * (qp * s2v + q * D21) + tt;

        float e00 = ux0, e11 = uy1, e01 = 0.5f * (ux1 + uy0);

        float ux00 = t3 * q * S100;
        float ux01 = t3 * (qp * D10 + q * S101);
        float ux11 = t3 * (2.0f * s1v + 2.0f * qp * D11 + q * S111);
        float uy00 = tt * q * S200;
        float uy01 = tt * (qp * D20 + q * S201);
        float uy11 = tt * (2.0f * s2v + 2.0f * qp * D21 + q * S211);

        float e00_0 = ux00, e00_1 = ux01;
        float e11_0 = uy01, e11_1 = uy11;
        float e01_0 = 0.5f * (ux01 + uy00);
        float e01_1 = 0.5f * (ux11 + uy01);

        float trc  = e00 + e11;
        float tr_0 = e00_0 + e11_0;
        float tr_1 = e00_1 + e11_1;

        float phi = 1.0f / (1.0f + expf(-s0));
        float sp  = phi * (1.0f - phi);
        float spp = sp * (1.0f - 2.0f * phi);
        float p0 = sp * D00, p1 = sp * D01, pt = sp * D0t;
        float p00 = spp * D00 * D00 + sp * S000;
        float p11 = spp * D01 * D01 + sp * S011;
        float lap = p00 + p11;

        float A  = fmaxf(trc, 0.0f);
        float Bn = fmaxf(-trc, 0.0f);
        float ppos = (trc > 0.0f) ? 1.0f : 0.0f;
        float pneg = (trc < 0.0f) ? 1.0f : 0.0f;
        float dd = e00 - e11;

        float omp = 1.0f - phi;
        float h   = omp * omp;
        float g   = h + 1e-6f;
        float hp0 = -2.0f * omp * p0;
        float hp1 = -2.0f * omp * p1;

        float P00 = 2.0f * A + dd;
        float P11 = 2.0f * A - dd;
        float P01 = 2.0f * e01;
        float s00 = g * P00 - 2.0f * Bn;
        float s11c = g * P11 - 2.0f * Bn;
        float s01 = g * P01;

        float P00_0 = 2.0f * ppos * tr_0 + (e00_0 - e11_0);
        float P11_1 = 2.0f * ppos * tr_1 - (e00_1 - e11_1);
        float P01_0 = 2.0f * e01_0;
        float P01_1 = 2.0f * e01_1;

        float s00_0 = hp0 * P00 + g * P00_0 + 2.0f * pneg * tr_0;
        float s11_1 = hp1 * P11 + g * P11_1 + 2.0f * pneg * tr_1;
        float s01_0 = hp0 * P01 + g * P01_0;
        float s01_1 = hp1 * P01 + g * P01_1;

        float res0 = hp0 * s00 + h * s00_0 + hp1 * s01 + h * s01_1;
        float res1 = hp0 * s01 + h * s01_0 + hp1 * s11c + h * s11_1;

        float psip = A * A + 0.5f * dd * dd + 2.0f * e01 * e01;
        float psin = Bn * Bn;

        const float GCc = 0.0027f, Lc = 0.02f;
        float pf = GCc * (phi / Lc - Lc * lap) - 2.0f * omp * psip;
        float dphidt = pt;
        bool mask_pos = (fabsf(dphidt) <= 1e-3f) && (fabsf(phi - 1.0f) > 1e-3f);
        bool mask_neg = (fabsf(phi - 1.0f) <= 1e-3f);
        float respf = mask_pos ? fmaxf(-pf, 0.0f) : (mask_neg ? fmaxf(pf, 0.0f) : pf);

        float rese = omp * 2.0f * psip + psin
                   + GCc * (phi * phi / (2.0f * Lc) + 0.5f * Lc * (p0 * p0 + p1 * p1));
        float rirr = fmaxf(-dphidt, 0.0f);

        atomicAdd(&sacc[0], (double)(res0 * res0));
        atomicAdd(&sacc[1], (double)(res1 * res1));
        atomicAdd(&sacc[2], (double)(respf * respf));
        atomicAdd(&sacc[3], (double)rese);
        atomicAdd(&sacc[4], (double)rirr);
    }
    __syncthreads();
    if (tid < 5) atomicAdd(&g_acc[tid], sacc[tid]);
}

// ---------------------------------------------------------------------------
__global__ void k_final(float* __restrict__ out) {
    double S0 = g_acc[0], S1 = g_acc[1], Spf = g_acc[2], Se = g_acc[3], Si = g_acc[4];
    double Nn = (double)NSAMP;
    double mse0 = S0 / Nn, mse1 = S1 / Nn;
    double m  = 0.5 * (mse0 + mse1);
    double w0 = m / (mse0 + 1e-6);
    double w1 = m / (mse1 + 1e-6);
    out[0] = (float)(w0 * mse0 + w1 * mse1);
    out[1] = (float)(Spf / Nn);
    out[2] = (float)log(Se);
    out[3] = (float)(Si / Nn);
}

// ---------------------------------------------------------------------------
extern "C" void kernel_launch(void* const* d_in, const int* in_sizes, int n_in,
                              void* d_out, int out_size) {
    const float *W[5], *b[5];
    if (n_in >= 2 && in_sizes[1] == HIDN) {
        for (int i = 0; i < 5; i++) {
            W[i] = (const float*)d_in[2 * i];
            b[i] = (const float*)d_in[2 * i + 1];
        }
    } else {
        for (int i = 0; i < 5; i++) {
            W[i] = (const float*)d_in[i];
            b[i] = (const float*)d_in[5 + i];
        }
    }
    const float* x = (const float*)d_in[10];
    const float* t = (const float*)d_in[11];

    __nv_bfloat16* pW;
    cudaGetSymbolAddress((void**)&pW, g_Wt);

    static bool attr_done = false;
    if (!attr_done) {
        cudaFuncSetAttribute(k_gemm, cudaFuncAttributeMaxDynamicSharedMemorySize, SMEMT);
        attr_done = true;
    }

    k_prepW<<<dim3(HIDN, 1, 3), HIDN>>>(W[1], W[2], W[3]);
    k_layer0<<<NSAMP, 256>>>(W[0], b[0], x, t);

    const int GRID = MTOT / MT;   // 512
    k_gemm<<<GRID, 256, SMEMT>>>(pW,                     b[1]);
    k_gemm<<<GRID, 256, SMEMT>>>(pW + HIDN * HIDN,       b[2]);
    k_gemm<<<GRID, 256, SMEMT>>>(pW + 2 * HIDN * HIDN,   b[3]);

    k_epi<<<NSAMP / 8, 256>>>(W[4], b[4], x, t);
    k_final<<<1, 1>>>((float*)d_out);
}

// round 5
// speedup vs baseline: 4.7535x; 1.7002x over previous
#include <cuda_runtime.h>
#include <cuda_fp16.h>
#include <cstdint>
#include <math.h>

#define NSAMP 8192
#define HIDN  256
#define MTOT  (7 * NSAMP)       // 57344 rows, interleaved: row = n*7 + c
#define MT    112               // rows per CTA tile (16 samples * 7 channels)
#define NT    128               // cols per CTA tile
#define SPC   16

// Jet channels: 0=val, 1=d/dx0, 2=d/dx1, 3=d/dt, 4=dx0dx0, 5=dx0dx1, 6=dx1dx1
__device__ __align__(256) __half g_A0[MTOT * HIDN];   // ping
__device__ __align__(256) __half g_A1[MTOT * HIDN];   // pong
__device__ __align__(256) __half g_Wt[3][HIDN * HIDN]; // W^T fp16: [n][k]
__device__ double g_acc[5];

// ---------------------------------------------------------------------------
__device__ __forceinline__ uint32_t smem_u32(const void* p) {
    uint32_t a;
    asm("{ .reg .u64 t; cvta.to.shared.u64 t, %1; cvt.u32.u64 %0, t; }" : "=r"(a) : "l"(p));
    return a;
}
__device__ __forceinline__ uint32_t sw128(uint32_t o) { return o ^ ((o >> 3) & 0x70); }

__device__ __forceinline__ void cpasync16(uint32_t s, const void* g) {
    asm volatile("cp.async.cg.shared.global [%0], [%1], 16;" :: "r"(s), "l"(g));
}
#define CP_COMMIT() asm volatile("cp.async.commit_group;" ::: "memory")

__device__ __forceinline__ void ldsm_x4(uint32_t* r, uint32_t a) {
    asm volatile("ldmatrix.sync.aligned.m8n8.x4.shared.b16 {%0,%1,%2,%3}, [%4];"
                 : "=r"(r[0]), "=r"(r[1]), "=r"(r[2]), "=r"(r[3]) : "r"(a));
}
__device__ __forceinline__ void ldsm_x2(uint32_t* r, uint32_t a) {
    asm volatile("ldmatrix.sync.aligned.m8n8.x2.shared.b16 {%0,%1}, [%2];"
                 : "=r"(r[0]), "=r"(r[1]) : "r"(a));
}
__device__ __forceinline__ void mma16816(float* d, const uint32_t* a, const uint32_t* b) {
    asm volatile(
        "mma.sync.aligned.m16n8k16.row.col.f32.f16.f16.f32 "
        "{%0,%1,%2,%3}, {%4,%5,%6,%7}, {%8,%9}, {%0,%1,%2,%3};"
        : "+f"(d[0]), "+f"(d[1]), "+f"(d[2]), "+f"(d[3])
        : "r"(a[0]), "r"(a[1]), "r"(a[2]), "r"(a[3]), "r"(b[0]), "r"(b[1]));
}

// ---------------------------------------------------------------------------
__global__ void k_prepW(const float* __restrict__ W1, const float* __restrict__ W2,
                        const float* __restrict__ W3) {
    int w = blockIdx.z;
    const float* W = (w == 0) ? W1 : ((w == 1) ? W2 : W3);
    int n = blockIdx.x, k = threadIdx.x;
    g_Wt[w][n * HIDN + k] = __float2half(W[k * HIDN + n]);
    if (w == 0 && n == 0 && k < 5) g_acc[k] = 0.0;
}

// Layer 0: input jets -> linear(W0,b0) -> tanh jet, interleaved row layout
__global__ void k_layer0(const float* __restrict__ W0, const float* __restrict__ b0,
                         const float* __restrict__ x,  const float* __restrict__ t) {
    int n = blockIdx.x, j = threadIdx.x;
    float x0 = x[2 * n], x1 = x[2 * n + 1], tv = t[n];
    float w0 = W0[j], w1 = W0[HIDN + j], w2 = W0[2 * HIDN + j];
    float zv = fmaf(x0, w0, fmaf(x1, w1, fmaf(tv, w2, b0[j])));
    float y = tanhf(zv);
    float yp = 1.0f - y * y;
    float ypp = -2.0f * y * yp;
    size_t base = ((size_t)n * 7) * HIDN + j;
    g_A0[base]            = __float2half(y);
    g_A0[base + HIDN]     = __float2half(yp * w0);
    g_A0[base + 2 * HIDN] = __float2half(yp * w1);
    g_A0[base + 3 * HIDN] = __float2half(yp * w2);
    g_A0[base + 4 * HIDN] = __float2half(ypp * w0 * w0);
    g_A0[base + 5 * HIDN] = __float2half(ypp * w0 * w1);
    g_A0[base + 6 * HIDN] = __float2half(ypp * w1 * w1);
}

// ---------------------------------------------------------------------------
// Fused fp16 GEMM + jet-tanh activation layer (ping-pong A buffers).
// CTA tile 112 x 128, warp tile 7mt x 2nt. K streamed in 4 chunks of 64.
#define ACH   14336                 // A chunk: 112 rows x 128B
#define BCH   16384                 // B chunk: 128 rows x 128B
#define BUF   (ACH + BCH)           // 30720
#define SMEMT (2 * BUF)             // 61440
#define ZS    132

__global__ void __launch_bounds__(256, 2) k_gemm(const __half* __restrict__ Asrc,
                                                 __half* __restrict__ Adst,
                                                 const __half* __restrict__ Bw,
                                                 const float* __restrict__ bias) {
    extern __shared__ char smem[];
    uint32_t sb = smem_u32(smem);
    int tid = threadIdx.x;
    int warp = tid >> 5, lane = tid & 31;
    int row0 = blockIdx.x * MT;
    int col0 = blockIdx.y * NT;

    float acc[7][2][4];
#pragma unroll
    for (int mt = 0; mt < 7; mt++)
#pragma unroll
        for (int nt = 0; nt < 2; nt++)
#pragma unroll
            for (int e = 0; e < 4; e++) acc[mt][nt][e] = 0.0f;

    auto load_chunk = [&](int c) {
        uint32_t base = sb + (c & 1) * BUF;
        int k0 = c * 64;
        for (int idx = tid; idx < 896; idx += 256) {
            int r = idx >> 3, u = idx & 7;
            cpasync16(base + sw128(r * 128 + u * 16),
                      Asrc + (size_t)(row0 + r) * HIDN + k0 + u * 8);
        }
        for (int idx = tid; idx < 1024; idx += 256) {
            int r = idx >> 3, u = idx & 7;
            cpasync16(base + ACH + sw128(r * 128 + u * 16),
                      Bw + (size_t)(col0 + r) * HIDN + k0 + u * 8);
        }
        CP_COMMIT();
    };

    load_chunk(0);

    int l8 = lane & 7;
    int qa_m8  = ((lane >> 3) & 1) * 8;
    int qa_k16 = (lane >> 4) * 16;
    int qb_k16 = ((lane >> 3) & 1) * 16;

    for (int c = 0; c < 4; c++) {
        if (c < 3) { load_chunk(c + 1); asm volatile("cp.async.wait_group 1;" ::: "memory"); }
        else       {                    asm volatile("cp.async.wait_group 0;" ::: "memory"); }
        __syncthreads();

        uint32_t abuf = sb + (c & 1) * BUF;
        uint32_t bbuf = abuf + ACH;
#pragma unroll
        for (int ks = 0; ks < 4; ks++) {
            uint32_t bf[2][2];
#pragma unroll
            for (int nt = 0; nt < 2; nt++) {
                int r = warp * 16 + nt * 8 + l8;
                ldsm_x2(bf[nt], bbuf + sw128(r * 128 + ks * 32 + qb_k16));
            }
            uint32_t af[7][4];
#pragma unroll
            for (int mt = 0; mt < 7; mt++) {
                int r = mt * 16 + qa_m8 + l8;
                ldsm_x4(af[mt], abuf + sw128(r * 128 + ks * 32 + qa_k16));
            }
#pragma unroll
            for (int mt = 0; mt < 7; mt++)
#pragma unroll
                for (int nt = 0; nt < 2; nt++)
                    mma16816(acc[mt][nt], af[mt], bf[nt]);
        }
        __syncthreads();
    }

    // ---- epilogue: accums -> smem staging, jet activation, fp16 out ----
    float* zb = (float*)smem;
#pragma unroll
    for (int mt = 0; mt < 7; mt++)
#pragma unroll
        for (int nt = 0; nt < 2; nt++)
#pragma unroll
            for (int e = 0; e < 4; e++) {
                int r = mt * 16 + (lane >> 2) + ((e >> 1) << 3);
                int col = warp * 16 + nt * 8 + ((lane & 3) << 1) + (e & 1);
                zb[r * ZS + col] = acc[mt][nt][e];
            }
    __syncthreads();

    for (int i = tid; i < SPC * NT; i += 256) {
        int nl = i >> 7, j = i & 127;
        int jg = col0 + j;
        const float* zrow = zb + (nl * 7) * ZS + j;
        float zv  = zrow[0] + bias[jg];
        float zg1 = zrow[ZS],     zg2 = zrow[2 * ZS], zg3 = zrow[3 * ZS];
        float zs11 = zrow[4 * ZS], zs12 = zrow[5 * ZS], zs22 = zrow[6 * ZS];
        float y = tanhf(zv);
        float yp = 1.0f - y * y;
        float ypp = -2.0f * y * yp;
        size_t gbase = ((size_t)(row0 + nl * 7)) * HIDN + jg;
        Adst[gbase]            = __float2half(y);
        Adst[gbase + HIDN]     = __float2half(yp * zg1);
        Adst[gbase + 2 * HIDN] = __float2half(yp * zg2);
        Adst[gbase + 3 * HIDN] = __float2half(yp * zg3);
        Adst[gbase + 4 * HIDN] = __float2half(fmaf(ypp * zg1, zg1, yp * zs11));
        Adst[gbase + 5 * HIDN] = __float2half(fmaf(ypp * zg1, zg2, yp * zs12));
        Adst[gbase + 6 * HIDN] = __float2half(fmaf(ypp * zg2, zg2, yp * zs22));
    }
}

// ---------------------------------------------------------------------------
// Physics epilogue: final 256->3 layer on all 7 jet channels + residuals.
__global__ void __launch_bounds__(256) k_epi(const __half* __restrict__ H,
                                             const float* __restrict__ W4,
                                             const float* __restrict__ b4,
                                             const float* __restrict__ x,
                                             const float* __restrict__ t) {
    __shared__ float  w4s[768];
    __shared__ float  b4s[3];
    __shared__ double sacc[5];
    int tid = threadIdx.x;
    if (tid < 5) sacc[tid] = 0.0;
    for (int i = tid; i < 768; i += 256) w4s[i] = W4[i];
    if (tid < 3) b4s[tid] = b4[tid];
    __syncthreads();

    int warp = tid >> 5, lane = tid & 31;
    int n = blockIdx.x * 8 + warp;

    float o[7][3];
#pragma unroll
    for (int c = 0; c < 7; c++)
#pragma unroll
        for (int a = 0; a < 3; a++) o[c][a] = 0.0f;

    for (int k = lane; k < HIDN; k += 32) {
        float wa = w4s[k * 3 + 0], wb = w4s[k * 3 + 1], wc = w4s[k * 3 + 2];
        size_t bidx = ((size_t)n * 7) * HIDN + k;
#pragma unroll
        for (int c = 0; c < 7; c++) {
            float hv = __half2float(H[bidx + (size_t)c * HIDN]);
            o[c][0] = fmaf(hv, wa, o[c][0]);
            o[c][1] = fmaf(hv, wb, o[c][1]);
            o[c][2] = fmaf(hv, wc, o[c][2]);
        }
    }
#pragma unroll
    for (int c = 0; c < 7; c++)
#pragma unroll
        for (int a = 0; a < 3; a++)
#pragma unroll
            for (int off = 16; off > 0; off >>= 1)
                o[c][a] += __shfl_xor_sync(0xFFFFFFFFu, o[c][a], off);

    if (lane == 0) {
        float s0  = o[0][0] + b4s[0];
        float s1v = o[0][1] + b4s[1];
        float s2v = o[0][2] + b4s[2];
        float D00 = o[1][0], D01 = o[2][0], D0t = o[3][0];
        float S000 = o[4][0], S011 = o[6][0];
        float D10 = o[1][1], D11 = o[2][1];
        float S100 = o[4][1], S101 = o[5][1], S111 = o[6][1];
        float D20 = o[1][2], D21 = o[2][2];
        float S200 = o[4][2], S201 = o[5][2], S211 = o[6][2];

        float x1 = x[2 * n + 1];
        float tt = t[n];
        float q  = x1 * (x1 - 1.0f);
        float qp = 2.0f * x1 - 1.0f;
        float t3 = tt / 3.0f;

        float ux0 = t3 * q * D10;
        float ux1 = t3 * (qp * s1v + q * D11);
        float uy0 = tt * q * D20;
        float uy1 = tt * (qp * s2v + q * D21) + tt;

        float e00 = ux0, e11 = uy1, e01 = 0.5f * (ux1 + uy0);

        float ux00 = t3 * q * S100;
        float ux01 = t3 * (qp * D10 + q * S101);
        float ux11 = t3 * (2.0f * s1v + 2.0f * qp * D11 + q * S111);
        float uy00 = tt * q * S200;
        float uy01 = tt * (qp * D20 + q * S201);
        float uy11 = tt * (2.0f * s2v + 2.0f * qp * D21 + q * S211);

        float e00_0 = ux00, e00_1 = ux01;
        float e11_0 = uy01, e11_1 = uy11;
        float e01_0 = 0.5f * (ux01 + uy00);
        float e01_1 = 0.5f * (ux11 + uy01);

        float trc  = e00 + e11;
        float tr_0 = e00_0 + e11_0;
        float tr_1 = e00_1 + e11_1;

        float phi = 1.0f / (1.0f + expf(-s0));
        float sp  = phi * (1.0f - phi);
        float spp = sp * (1.0f - 2.0f * phi);
        float p0 = sp * D00, p1 = sp * D01, pt = sp * D0t;
        float p00 = spp * D00 * D00 + sp * S000;
        float p11 = spp * D01 * D01 + sp * S011;
        float lap = p00 + p11;

        float A  = fmaxf(trc, 0.0f);
        float Bn = fmaxf(-trc, 0.0f);
        float ppos = (trc > 0.0f) ? 1.0f : 0.0f;
        float pneg = (trc < 0.0f) ? 1.0f : 0.0f;
        float dd = e00 - e11;

        float omp = 1.0f - phi;
        float h   = omp * omp;
        float g   = h + 1e-6f;
        float hp0 = -2.0f * omp * p0;
        float hp1 = -2.0f * omp * p1;

        float P00 = 2.0f * A + dd;
        float P11 = 2.0f * A - dd;
        float P01 = 2.0f * e01;
        float s00 = g * P00 - 2.0f * Bn;
        float s11c = g * P11 - 2.0f * Bn;
        float s01 = g * P01;

        float P00_0 = 2.0f * ppos * tr_0 + (e00_0 - e11_0);
        float P11_1 = 2.0f * ppos * tr_1 - (e00_1 - e11_1);
        float P01_0 = 2.0f * e01_0;
        float P01_1 = 2.0f * e01_1;

        float s00_0 = hp0 * P00 + g * P00_0 + 2.0f * pneg * tr_0;
        float s11_1 = hp1 * P11 + g * P11_1 + 2.0f * pneg * tr_1;
        float s01_0 = hp0 * P01 + g * P01_0;
        float s01_1 = hp1 * P01 + g * P01_1;

        float res0 = hp0 * s00 + h * s00_0 + hp1 * s01 + h * s01_1;
        float res1 = hp0 * s01 + h * s01_0 + hp1 * s11c + h * s11_1;

        float psip = A * A + 0.5f * dd * dd + 2.0f * e01 * e01;
        float psin = Bn * Bn;

        const float GCc = 0.0027f, Lc = 0.02f;
        float pf = GCc * (phi / Lc - Lc * lap) - 2.0f * omp * psip;
        float dphidt = pt;
        bool mask_pos = (fabsf(dphidt) <= 1e-3f) && (fabsf(phi - 1.0f) > 1e-3f);
        bool mask_neg = (fabsf(phi - 1.0f) <= 1e-3f);
        float respf = mask_pos ? fmaxf(-pf, 0.0f) : (mask_neg ? fmaxf(pf, 0.0f) : pf);

        float rese = omp * 2.0f * psip + psin
                   + GCc * (phi * phi / (2.0f * Lc) + 0.5f * Lc * (p0 * p0 + p1 * p1));
        float rirr = fmaxf(-dphidt, 0.0f);

        atomicAdd(&sacc[0], (double)(res0 * res0));
        atomicAdd(&sacc[1], (double)(res1 * res1));
        atomicAdd(&sacc[2], (double)(respf * respf));
        atomicAdd(&sacc[3], (double)rese);
        atomicAdd(&sacc[4], (double)rirr);
    }
    __syncthreads();
    if (tid < 5) atomicAdd(&g_acc[tid], sacc[tid]);
}

// ---------------------------------------------------------------------------
__global__ void k_final(float* __restrict__ out) {
    double S0 = g_acc[0], S1 = g_acc[1], Spf = g_acc[2], Se = g_acc[3], Si = g_acc[4];
    double Nn = (double)NSAMP;
    double mse0 = S0 / Nn, mse1 = S1 / Nn;
    double m  = 0.5 * (mse0 + mse1);
    double w0 = m / (mse0 + 1e-6);
    double w1 = m / (mse1 + 1e-6);
    out[0] = (float)(w0 * mse0 + w1 * mse1);
    out[1] = (float)(Spf / Nn);
    out[2] = (float)log(Se);
    out[3] = (float)(Si / Nn);
}

// ---------------------------------------------------------------------------
extern "C" void kernel_launch(void* const* d_in, const int* in_sizes, int n_in,
                              void* d_out, int out_size) {
    const float *W[5], *b[5];
    if (n_in >= 2 && in_sizes[1] == HIDN) {
        for (int i = 0; i < 5; i++) {
            W[i] = (const float*)d_in[2 * i];
            b[i] = (const float*)d_in[2 * i + 1];
        }
    } else {
        for (int i = 0; i < 5; i++) {
            W[i] = (const float*)d_in[i];
            b[i] = (const float*)d_in[5 + i];
        }
    }
    const float* x = (const float*)d_in[10];
    const float* t = (const float*)d_in[11];

    __half *pA0, *pA1, *pW;
    cudaGetSymbolAddress((void**)&pA0, g_A0);
    cudaGetSymbolAddress((void**)&pA1, g_A1);
    cudaGetSymbolAddress((void**)&pW,  g_Wt);

    static bool attr_done = false;
    if (!attr_done) {
        cudaFuncSetAttribute(k_gemm, cudaFuncAttributeMaxDynamicSharedMemorySize, SMEMT);
        attr_done = true;
    }

    k_prepW<<<dim3(HIDN, 1, 3), HIDN>>>(W[1], W[2], W[3]);
    k_layer0<<<NSAMP, 256>>>(W[0], b[0], x, t);

    dim3 gg(MTOT / MT, HIDN / NT);   // (512, 2)
    k_gemm<<<gg, 256, SMEMT>>>(pA0, pA1, pW,                   b[1]);
    k_gemm<<<gg, 256, SMEMT>>>(pA1, pA0, pW + HIDN * HIDN,     b[2]);
    k_gemm<<<gg, 256, SMEMT>>>(pA0, pA1, pW + 2 * HIDN * HIDN, b[3]);

    k_epi<<<NSAMP / 8, 256>>>(pA1, W[4], b[4], x, t);
    k_final<<<1, 1>>>((float*)d_out);
}